// round 5
// baseline (speedup 1.0000x reference)
#include <cuda_runtime.h>

#define HH 200
#define WW 320
#define CC 256
#define RR 128
#define MM 14
#define HWSZ (HH*WW)

// Scratch: transposed feature [H*W, C] and per-bin maxima. Static device
// globals (allowed; no runtime allocation).
__device__ float g_featT[HWSZ * CC];
__device__ __align__(16) float g_bin[MM * MM];

// -------------------------------------------------------------------------
__global__ void init_bins_kernel() {
    if (threadIdx.x < MM * MM)
        g_bin[threadIdx.x] = __int_as_float(0xff800000); // -inf
}

// -------------------------------------------------------------------------
// Transpose [C, H*W] -> [H*W, C], 32x32 tiles. 64000 = 2000*32, 256 = 8*32.
__global__ void transpose_kernel(const float* __restrict__ f) {
    __shared__ float tile[32][33];
    int hw0 = blockIdx.x * 32;
    int c0  = blockIdx.y * 32;
    int tx = threadIdx.x;   // 0..31
    int ty = threadIdx.y;   // 0..7
#pragma unroll
    for (int j = 0; j < 32; j += 8)
        tile[ty + j][tx] = f[(size_t)(c0 + ty + j) * HWSZ + hw0 + tx];
    __syncthreads();
#pragma unroll
    for (int j = 0; j < 32; j += 8)
        g_featT[(size_t)(hw0 + ty + j) * CC + c0 + tx] = tile[tx][ty + j];
}

// -------------------------------------------------------------------------
__device__ __forceinline__ void atomicMaxFloat(float* addr, float val) {
    if (val >= 0.0f) {
        atomicMax((int*)addr, __float_as_int(val));
    } else {
        // negative floats order-reverse as unsigned ints; positives have
        // smaller uint bits than negatives, so atomicMin(uint) is a no-op
        // against any stored positive value and correct among negatives.
        atomicMin((unsigned int*)addr, __float_as_uint(val));
    }
}

// grid: (196 bins, 8 roi-chunks of 16), block: 256 threads = 8 warps.
// Each warp processes tasks (roi, sample-pt); lanes span channels.
__global__ void roi_max_kernel(const float* __restrict__ rois) {
    const int bin  = blockIdx.x;
    const int m    = bin / MM;
    const int n    = bin % MM;
    const int warp = threadIdx.x >> 5;
    const int lane = threadIdx.x & 31;
    const int r0   = blockIdx.y * 16;

    float vmax = __int_as_float(0xff800000);

    for (int t = warp; t < 64; t += 8) {
        const int r  = r0 + (t >> 2);
        const int pt = t & 3;

        const float ry = rois[r * 4 + 0];
        const float rx = rois[r * 4 + 1];
        const float sh = (rois[r * 4 + 2] - ry) / 14.0f;
        const float sw = (rois[r * 4 + 3] - rx) / 14.0f;

        const float fr = (pt & 2) ? (2.0f / 3.0f) : (1.0f / 3.0f);
        const float fc = (pt & 1) ? (2.0f / 3.0f) : (1.0f / 3.0f);

        // Match reference order: (roi + s*m) + s*frac
        const float y = (ry + sh * (float)m) + sh * fr;
        const float x = (rx + sw * (float)n) + sw * fc;

        const int yf = (int)floorf(y);
        const int y1 = min(max(yf, 0), HH - 1);
        const int y2 = min(max(yf + 1, 0), HH - 1);
        const int xf = (int)floorf(x);
        const int x1 = min(max(xf, 0), WW - 1);
        const int x2 = min(max(xf + 1, 0), WW - 1);

        // Reference computes weights from the *clamped* corner indices.
        const float wy_lo = y - (float)y1;
        const float wy_hi = (float)y2 - y;
        const float wx_lo = x - (float)x1;
        const float wx_hi = (float)x2 - x;

        const float4* p11 = (const float4*)(g_featT + (size_t)(y1 * WW + x1) * CC);
        const float4* p12 = (const float4*)(g_featT + (size_t)(y1 * WW + x2) * CC);
        const float4* p21 = (const float4*)(g_featT + (size_t)(y2 * WW + x1) * CC);
        const float4* p22 = (const float4*)(g_featT + (size_t)(y2 * WW + x2) * CC);

#pragma unroll
        for (int k = 0; k < 2; k++) {
            const int ci = lane + k * 32; // float4 index -> channels 4*ci..4*ci+3
            const float4 a = p11[ci];
            const float4 b = p12[ci];
            const float4 c = p21[ci];
            const float4 d = p22[ci];
            float4 v;
            v.x = (a.x * wx_hi + b.x * wx_lo) * wy_hi + (c.x * wx_hi + d.x * wx_lo) * wy_lo;
            v.y = (a.y * wx_hi + b.y * wx_lo) * wy_hi + (c.y * wx_hi + d.y * wx_lo) * wy_lo;
            v.z = (a.z * wx_hi + b.z * wx_lo) * wy_hi + (c.z * wx_hi + d.z * wx_lo) * wy_lo;
            v.w = (a.w * wx_hi + b.w * wx_lo) * wy_hi + (c.w * wx_hi + d.w * wx_lo) * wy_lo;
            vmax = fmaxf(vmax, fmaxf(fmaxf(v.x, v.y), fmaxf(v.z, v.w)));
        }
    }

    // warp reduce
#pragma unroll
    for (int o = 16; o > 0; o >>= 1)
        vmax = fmaxf(vmax, __shfl_xor_sync(0xffffffffu, vmax, o));

    __shared__ float sred[8];
    if (lane == 0) sred[warp] = vmax;
    __syncthreads();
    if (threadIdx.x == 0) {
        float v = sred[0];
#pragma unroll
        for (int i = 1; i < 8; i++) v = fmaxf(v, sred[i]);
        atomicMaxFloat(&g_bin[bin], v);
    }
}

// -------------------------------------------------------------------------
// out[r,c,m,n] = bin[m,n]; inner period 196 floats = 49 float4s exactly.
__global__ void broadcast_kernel(float4* __restrict__ out) {
    __shared__ float4 sb[49];
    if (threadIdx.x < 49)
        sb[threadIdx.x] = ((const float4*)g_bin)[threadIdx.x];
    __syncthreads();
    const int j = blockIdx.x * blockDim.x + threadIdx.x;
    // total float4 = 128*256*196/4 = 1,605,632 = 6272 * 256 (exact)
    out[j] = sb[j % 49];
}

// -------------------------------------------------------------------------
extern "C" void kernel_launch(void* const* d_in, const int* in_sizes, int n_in,
                              void* d_out, int out_size) {
    const float* feature = (const float*)d_in[0]; // [1,256,200,320]
    const float* rois    = (const float*)d_in[1]; // [128,4]
    float* out           = (float*)d_out;         // [128,256,14,14]
    (void)in_sizes; (void)n_in; (void)out_size;

    init_bins_kernel<<<1, 256>>>();
    transpose_kernel<<<dim3(HWSZ / 32, CC / 32), dim3(32, 8)>>>(feature);
    roi_max_kernel<<<dim3(MM * MM, 8), 256>>>(rois);
    broadcast_kernel<<<(RR * CC * MM * MM / 4) / 256, 256>>>((float4*)out);
}